// round 15
// baseline (speedup 1.0000x reference)
#include <cuda_runtime.h>
#include <cuda_bf16.h>
#include <cstdint>

// ---------------------------------------------------------------------------
// BarrierNet on GB300, round 15: R14 (committed 79.8us) + ONE delta:
// tanh.approx.bf16x2 in gemm epilogues + fc1 (halves MUFU ops; MUFU-saturation
// model predicts the xu pipe is the binding resource at ~142k cyc/SM).
// Everything else byte-identical to R14: 256 thr, 2 CTA/SM, 4x2 warp tiling,
// bf16 m16n8k16 mma.sync, cp.async blob staging, 64-CTA prep kernel.
// ---------------------------------------------------------------------------

#define THREADS 256
#define ROWS_PER_CTA 128
#define STRB 136            // bf16 elems per smem row -> 4g+tg bank permutation
#define ROWB (STRB * 2)     // 272 bytes per row
#define WBUF_BYTES 35328    // 128*272 weight rows + 512B fp32 bias

// byte offsets into dynamic smem
#define OFF_W    0                      // staged weights + bias (35328 B)
#define OFF_H    35328                  // 128 x STRB bf16
#define OFF_A    70144                  // 128 x STRB bf16
#define OFF_X    104960                 // 128*6 f32
#define OFF_W1   108032                 // 768 f32
#define OFF_B1   111104                 // 128 f32
#define OFF_W31  111616                 // 384 f32
#define OFF_W32  113152                 // 256 f32
#define OFF_SML  114176                 // 17 f32: b31[0..2] b32[3..4] std[5..10] mean[11..16]
#define SMEM_BYTES 114304

__device__ __align__(16) unsigned char g_wbuf[4][WBUF_BYTES];

__device__ __forceinline__ uint32_t smem_u32(const void* p) {
    uint32_t a;
    asm("{ .reg .u64 t; cvta.to.shared.u64 t, %1; cvt.u32.u64 %0, t; }"
        : "=r"(a) : "l"(p));
    return a;
}

__device__ __forceinline__ void ldsm4(uint32_t& r0, uint32_t& r1, uint32_t& r2, uint32_t& r3,
                                      uint32_t addr) {
    asm volatile("ldmatrix.sync.aligned.m8n8.x4.shared.b16 {%0,%1,%2,%3}, [%4];"
                 : "=r"(r0), "=r"(r1), "=r"(r2), "=r"(r3) : "r"(addr));
}

__device__ __forceinline__ void mma_bf16(float& c0, float& c1, float& c2, float& c3,
                                         uint32_t a0, uint32_t a1, uint32_t a2, uint32_t a3,
                                         uint32_t b0, uint32_t b1) {
    asm volatile(
        "mma.sync.aligned.m16n8k16.row.col.f32.bf16.bf16.f32 "
        "{%0,%1,%2,%3}, {%4,%5,%6,%7}, {%8,%9}, {%0,%1,%2,%3};\n"
        : "+f"(c0), "+f"(c1), "+f"(c2), "+f"(c3)
        : "r"(a0), "r"(a1), "r"(a2), "r"(a3), "r"(b0), "r"(b1));
}

__device__ __forceinline__ uint32_t pack_bf2(float lo, float hi) {
    __nv_bfloat162 h = __floats2bfloat162_rn(lo, hi);
    return *reinterpret_cast<uint32_t*>(&h);
}

__device__ __forceinline__ uint32_t tanh2(uint32_t v) {
    asm("tanh.approx.bf16x2 %0, %0;" : "+r"(v));
    return v;
}

// ---------------- prep kernel: 64 CTAs, 8 weight rows each ------------------
__global__ void prep_weights(const float* __restrict__ w21, const float* __restrict__ b21,
                             const float* __restrict__ wm1, const float* __restrict__ bm1,
                             const float* __restrict__ w22, const float* __restrict__ b22,
                             const float* __restrict__ wm2, const float* __restrict__ bm2) {
    const float* W[4]  = {w21, wm1, w22, wm2};
    const float* Bv[4] = {b21, bm1, b22, bm2};
    const int m = blockIdx.x >> 4;
    const int chunk = blockIdx.x & 15;
    unsigned char* dst = g_wbuf[m];
    const float* src = W[m];
    const int r0 = chunk * 8;
    for (int i = threadIdx.x; i < 8 * 68; i += blockDim.x) {
        int r = r0 + i / 68, p = i % 68;
        uint32_t val = 0;
        if (p < 64) {
            float2 v = reinterpret_cast<const float2*>(src)[r * 64 + p];
            val = pack_bf2(v.x, v.y);
        }
        reinterpret_cast<uint32_t*>(dst + r * ROWB)[p] = val;
    }
    if (chunk == 0 && threadIdx.x < 128)
        reinterpret_cast<float*>(dst + 128 * ROWB)[threadIdx.x] = Bv[m][threadIdx.x];
}

// ---------------- cp.async weight staging ----------------------------------
__device__ __forceinline__ void cp_issue(char* sb, int midx, int tid) {
    uint32_t wbase = smem_u32(sb) + OFF_W;
    const unsigned char* g = g_wbuf[midx];
    #pragma unroll
    for (int it = 0; it < 9; ++it) {
        int i = tid + it * THREADS;
        if (i < WBUF_BYTES / 16) {
            asm volatile("cp.async.cg.shared.global [%0], [%1], 16;"
                         :: "r"(wbase + i * 16),
                            "l"(__cvta_generic_to_global(g + i * 16)));
        }
    }
    asm volatile("cp.async.commit_group;");
}

__device__ __forceinline__ void cp_wait() {
    asm volatile("cp.async.wait_group 0;");
    __syncthreads();
}

// ---------------- one 128x128x128 layer, 4x2 warp tiling --------------------
// warp w: rows [32*(w&3), +32), cols [64*(w>>2), +64). out = tanh(in @ W^T + b).
// Always writes OFF_A; in_off may equal OFF_A (barrier separates read/write).
__device__ __forceinline__ void gemm_tanh(char* sb, int in_off, int warp, int lane) {
    const int rw = warp & 3, cw = warp >> 2;
    const int g = lane >> 2, tg = lane & 3;
    float acc[2][8][4];
    #pragma unroll
    for (int mt = 0; mt < 2; ++mt)
        #pragma unroll
        for (int t = 0; t < 8; ++t)
            acc[mt][t][0] = acc[mt][t][1] = acc[mt][t][2] = acc[mt][t][3] = 0.f;

    const uint32_t base = smem_u32(sb);
    const int l7 = lane & 7;
    const int rA = (((lane >> 3) & 1) << 3) + l7;
    const int kA = (lane >> 4) << 3;
    uint32_t aaddr0 = base + in_off + (rw * 32 + rA) * ROWB + kA * 2;
    uint32_t aaddr1 = aaddr0 + 16 * ROWB;
    const int rB = (((lane >> 4) & 1) << 3) + l7;
    const int kB = ((lane >> 3) & 1) << 3;
    uint32_t baddr = base + OFF_W + (cw * 64 + rB) * ROWB + kB * 2;

    #pragma unroll
    for (int kk = 0; kk < 8; ++kk) {
        uint32_t a0, a1, a2, a3, a4, a5, a6, a7;
        ldsm4(a0, a1, a2, a3, aaddr0 + kk * 32);
        ldsm4(a4, a5, a6, a7, aaddr1 + kk * 32);
        #pragma unroll
        for (int np = 0; np < 4; ++np) {
            uint32_t b0, b1, b2, b3;
            ldsm4(b0, b1, b2, b3, baddr + np * (16 * ROWB) + kk * 32);
            mma_bf16(acc[0][2*np][0],   acc[0][2*np][1],   acc[0][2*np][2],   acc[0][2*np][3],
                     a0, a1, a2, a3, b0, b1);
            mma_bf16(acc[0][2*np+1][0], acc[0][2*np+1][1], acc[0][2*np+1][2], acc[0][2*np+1][3],
                     a0, a1, a2, a3, b2, b3);
            mma_bf16(acc[1][2*np][0],   acc[1][2*np][1],   acc[1][2*np][2],   acc[1][2*np][3],
                     a4, a5, a6, a7, b0, b1);
            mma_bf16(acc[1][2*np+1][0], acc[1][2*np+1][1], acc[1][2*np+1][2], acc[1][2*np+1][3],
                     a4, a5, a6, a7, b2, b3);
        }
    }
    __syncthreads();  // all warps' reads of in_off/A complete before stores

    const float* bias = reinterpret_cast<const float*>(sb + OFF_W + 128 * ROWB);
    #pragma unroll
    for (int mt = 0; mt < 2; ++mt) {
        char* o0 = sb + OFF_A + (rw * 32 + mt * 16 + g) * ROWB + cw * 128;
        #pragma unroll
        for (int t = 0; t < 8; ++t) {
            int c = cw * 64 + t * 8 + tg * 2;
            float b0 = bias[c], b1 = bias[c + 1];
            uint32_t p0 = tanh2(pack_bf2(acc[mt][t][0] + b0, acc[mt][t][1] + b1));
            uint32_t p1 = tanh2(pack_bf2(acc[mt][t][2] + b0, acc[mt][t][3] + b1));
            *reinterpret_cast<uint32_t*>(o0 + (t * 8 + tg * 2) * 2) = p0;
            *reinterpret_cast<uint32_t*>(o0 + 8 * ROWB + (t * 8 + tg * 2) * 2) = p1;
        }
    }
}

__global__ void __launch_bounds__(THREADS, 2)
barriernet_kernel(const float* __restrict__ x,
                  const float* __restrict__ mean_, const float* __restrict__ std_,
                  const float* __restrict__ fc1_w, const float* __restrict__ fc1_b,
                  const float* __restrict__ fc31_w, const float* __restrict__ fc31_b,
                  const float* __restrict__ fc32_w, const float* __restrict__ fc32_b,
                  float* __restrict__ out)
{
    extern __shared__ char sb[];
    const int tid  = threadIdx.x;
    const int warp = tid >> 5;
    const int lane = tid & 31;
    const int row0 = blockIdx.x * ROWS_PER_CTA;

    // ---- stage small constants + x tile ----
    float* xs   = reinterpret_cast<float*>(sb + OFF_X);
    float* w1s  = reinterpret_cast<float*>(sb + OFF_W1);
    float* b1s  = reinterpret_cast<float*>(sb + OFF_B1);
    float* w31s = reinterpret_cast<float*>(sb + OFF_W31);
    float* w32s = reinterpret_cast<float*>(sb + OFF_W32);
    float* sml  = reinterpret_cast<float*>(sb + OFF_SML);
    for (int i = tid; i < 768; i += THREADS) { xs[i] = x[(size_t)row0 * 6 + i]; w1s[i] = fc1_w[i]; }
    for (int i = tid; i < 384; i += THREADS) w31s[i] = fc31_w[i];
    for (int i = tid; i < 256; i += THREADS) w32s[i] = fc32_w[i];
    if (tid < 128) b1s[tid] = fc1_b[tid];
    if (tid < 3)  sml[tid] = fc31_b[tid];
    if (tid >= 3 && tid < 5) sml[tid] = fc32_b[tid - 3];
    if (tid >= 5 && tid < 11) sml[tid] = std_[tid - 5];
    if (tid >= 11 && tid < 17) sml[tid] = mean_[tid - 11];
    __syncthreads();

    // prefetch fc21 weights, overlapped with fc1 compute
    cp_issue(sb, 0, tid);

    // ---- fc1 (K=6) + tanh2 -> H (bf16), adjacent col pair per lane step ----
    #pragma unroll
    for (int r = 0; r < 16; ++r) {
        int row = warp * 16 + r;
        const float* xr = &xs[row * 6];
        float x0v = xr[0], x1v = xr[1], x2v = xr[2], x3v = xr[3], x4v = xr[4], x5v = xr[5];
        #pragma unroll
        for (int cp = lane; cp < 64; cp += 32) {
            const float* wA = &w1s[(2 * cp) * 6];
            const float* wB = wA + 6;
            float sA = b1s[2 * cp]     + x0v*wA[0] + x1v*wA[1] + x2v*wA[2] + x3v*wA[3] + x4v*wA[4] + x5v*wA[5];
            float sB = b1s[2 * cp + 1] + x0v*wB[0] + x1v*wB[1] + x2v*wB[2] + x3v*wB[3] + x4v*wB[4] + x5v*wB[5];
            *reinterpret_cast<uint32_t*>(sb + OFF_H + row * ROWB + cp * 4) =
                tanh2(pack_bf2(sA, sB));
        }
    }
    cp_wait();  // fc21 staged; barrier also publishes H

    // ---- path 1: fc21 -> fcm1 -> fc31 head ----
    gemm_tanh(sb, OFF_H, warp, lane);
    cp_issue(sb, 1, tid);   // fcm1 (W region free: all MMA reads done pre-store)
    cp_wait();
    gemm_tanh(sb, OFF_A, warp, lane);
    __syncthreads();        // publish A for head reads across warps

    float d0 = 0.f, d1 = 0.f, d2 = 0.f;
    if (lane < 16) {
        int row = warp * 16 + lane;
        const uint32_t* a = reinterpret_cast<const uint32_t*>(sb + OFF_A + row * ROWB);
        d0 = sml[0]; d1 = sml[1]; d2 = sml[2];
        #pragma unroll 8
        for (int i = 0; i < 64; ++i) {
            uint32_t u = a[i];
            float2 av = __bfloat1622float2(*reinterpret_cast<const __nv_bfloat162*>(&u));
            int k = 2 * i;
            d0 += av.x * w31s[k]       + av.y * w31s[k + 1];
            d1 += av.x * w31s[128 + k] + av.y * w31s[128 + k + 1];
            d2 += av.x * w31s[256 + k] + av.y * w31s[256 + k + 1];
        }
    }

    // ---- path 2: fc22 -> fcm2 -> fc32 head + HOCBF/QP epilogue ----
    cp_issue(sb, 2, tid);   // fc22
    cp_wait();
    gemm_tanh(sb, OFF_H, warp, lane);   // internal barrier also fences head1 A-reads
    cp_issue(sb, 3, tid);   // fcm2
    cp_wait();
    gemm_tanh(sb, OFF_A, warp, lane);
    __syncthreads();

    if (lane < 16) {
        int row = warp * 16 + lane;
        const uint32_t* a = reinterpret_cast<const uint32_t*>(sb + OFF_A + row * ROWB);
        float z0 = sml[3], z1 = sml[4];
        #pragma unroll 8
        for (int i = 0; i < 64; ++i) {
            uint32_t u = a[i];
            float2 av = __bfloat1622float2(*reinterpret_cast<const __nv_bfloat162*>(&u));
            int k = 2 * i;
            z0 += av.x * w32s[k]       + av.y * w32s[k + 1];
            z1 += av.x * w32s[128 + k] + av.y * w32s[128 + k + 1];
        }
        float s0 = 4.f / (1.f + expf(-z0));
        float s1 = 4.f / (1.f + expf(-z1));

        const float* xr = &xs[row * 6];
        float px = xr[0] * sml[5] + sml[11];
        float vx = xr[1] * sml[6] + sml[12];
        float py = xr[2] * sml[7] + sml[13];
        float vy = xr[3] * sml[8] + sml[14];
        float pz = xr[4] * sml[9] + sml[15];
        float vz = xr[5] * sml[10] + sml[16];

        float dx = px - 10.f, dy = py - 10.f, dz = pz - 9.f;
        float dx2 = dx*dx, dy2 = dy*dy, dz2 = dz*dz;
        float dx3 = dx2*dx, dy3 = dy2*dy, dz3 = dz2*dz;
        float barrier = dx2*dx2 + dy2*dy2 + dz2*dz2 - 2401.f;  // R^4
        float bdot = 4.f * (dx3*vx + dy3*vy + dz3*vz);
        float Lf2b = 12.f * (dx2*vx*vx + dy2*vy*vy + dz2*vz*vz);
        float Gx = -4.f*dx3, Gy = -4.f*dy3, Gz = -4.f*dz3;
        float hv = Lf2b + (s0 + s1) * bdot + s0 * s1 * barrier;

        float u0 = -d0, u1 = -d1, u2 = -d2;
        float Gu = Gx*u0 + Gy*u1 + Gz*u2;
        float GG = Gx*Gx + Gy*Gy + Gz*Gz;
        float lam = fmaxf(Gu - hv, 0.f) / GG;

        float* o = out + (size_t)(row0 + row) * 3;
        o[0] = u0 - lam * Gx;
        o[1] = u1 - lam * Gy;
        o[2] = u2 - lam * Gz;
    }
}

extern "C" void kernel_launch(void* const* d_in, const int* in_sizes, int n_in,
                              void* d_out, int out_size) {
    const float* x      = (const float*)d_in[0];
    const float* mean_  = (const float*)d_in[1];
    const float* std_   = (const float*)d_in[2];
    const float* fc1_w  = (const float*)d_in[3];
    const float* fc1_b  = (const float*)d_in[4];
    const float* fc21_w = (const float*)d_in[5];
    const float* fc21_b = (const float*)d_in[6];
    const float* fc22_w = (const float*)d_in[7];
    const float* fc22_b = (const float*)d_in[8];
    const float* fcm1_w = (const float*)d_in[9];
    const float* fcm1_b = (const float*)d_in[10];
    const float* fcm2_w = (const float*)d_in[11];
    const float* fcm2_b = (const float*)d_in[12];
    const float* fc31_w = (const float*)d_in[13];
    const float* fc31_b = (const float*)d_in[14];
    const float* fc32_w = (const float*)d_in[15];
    const float* fc32_b = (const float*)d_in[16];
    float* out = (float*)d_out;

    int B = in_sizes[0] / 6;
    int grid = B / ROWS_PER_CTA;

    prep_weights<<<64, 256>>>(fc21_w, fc21_b, fcm1_w, fcm1_b,
                              fc22_w, fc22_b, fcm2_w, fcm2_b);

    cudaFuncSetAttribute(barriernet_kernel,
                         cudaFuncAttributeMaxDynamicSharedMemorySize, SMEM_BYTES);
    barriernet_kernel<<<grid, THREADS, SMEM_BYTES>>>(
        x, mean_, std_, fc1_w, fc1_b, fc31_w, fc31_b, fc32_w, fc32_b, out);
}

// round 16
// speedup vs baseline: 1.1442x; 1.1442x over previous
#include <cuda_runtime.h>
#include <cuda_bf16.h>
#include <cstdint>

// ---------------------------------------------------------------------------
// BarrierNet on GB300, round 16: R14 (committed best, 79.8us) + ONE delta:
// bias folded into MMA accumulator init (acc starts at bias, not 0) —
// deletes 64 FADD + 16 LDS per thread-layer from the epilogue, register-
// neutral. Everything else byte-identical to R14.
// ---------------------------------------------------------------------------

#define THREADS 256
#define ROWS_PER_CTA 128
#define STRB 136            // bf16 elems per smem row -> 4g+tg bank permutation
#define ROWB (STRB * 2)     // 272 bytes per row
#define WBUF_BYTES 35328    // 128*272 weight rows + 512B fp32 bias

// byte offsets into dynamic smem
#define OFF_W    0                      // staged weights + bias (35328 B)
#define OFF_H    35328                  // 128 x STRB bf16
#define OFF_A    70144                  // 128 x STRB bf16
#define OFF_X    104960                 // 128*6 f32
#define OFF_W1   108032                 // 768 f32
#define OFF_B1   111104                 // 128 f32
#define OFF_W31  111616                 // 384 f32
#define OFF_W32  113152                 // 256 f32
#define OFF_SML  114176                 // 17 f32: b31[0..2] b32[3..4] std[5..10] mean[11..16]
#define SMEM_BYTES 114304

__device__ __align__(16) unsigned char g_wbuf[4][WBUF_BYTES];

__device__ __forceinline__ uint32_t smem_u32(const void* p) {
    uint32_t a;
    asm("{ .reg .u64 t; cvta.to.shared.u64 t, %1; cvt.u32.u64 %0, t; }"
        : "=r"(a) : "l"(p));
    return a;
}

__device__ __forceinline__ void ldsm4(uint32_t& r0, uint32_t& r1, uint32_t& r2, uint32_t& r3,
                                      uint32_t addr) {
    asm volatile("ldmatrix.sync.aligned.m8n8.x4.shared.b16 {%0,%1,%2,%3}, [%4];"
                 : "=r"(r0), "=r"(r1), "=r"(r2), "=r"(r3) : "r"(addr));
}

__device__ __forceinline__ void mma_bf16(float& c0, float& c1, float& c2, float& c3,
                                         uint32_t a0, uint32_t a1, uint32_t a2, uint32_t a3,
                                         uint32_t b0, uint32_t b1) {
    asm volatile(
        "mma.sync.aligned.m16n8k16.row.col.f32.bf16.bf16.f32 "
        "{%0,%1,%2,%3}, {%4,%5,%6,%7}, {%8,%9}, {%0,%1,%2,%3};\n"
        : "+f"(c0), "+f"(c1), "+f"(c2), "+f"(c3)
        : "r"(a0), "r"(a1), "r"(a2), "r"(a3), "r"(b0), "r"(b1));
}

__device__ __forceinline__ float tanh_fast(float x) {
    asm("tanh.approx.f32 %0, %0;" : "+f"(x));
    return x;
}

__device__ __forceinline__ uint32_t pack_bf2(float lo, float hi) {
    __nv_bfloat162 h = __floats2bfloat162_rn(lo, hi);
    return *reinterpret_cast<uint32_t*>(&h);
}

// ---------------- prep kernel: 64 CTAs, 8 weight rows each ------------------
__global__ void prep_weights(const float* __restrict__ w21, const float* __restrict__ b21,
                             const float* __restrict__ wm1, const float* __restrict__ bm1,
                             const float* __restrict__ w22, const float* __restrict__ b22,
                             const float* __restrict__ wm2, const float* __restrict__ bm2) {
    const float* W[4]  = {w21, wm1, w22, wm2};
    const float* Bv[4] = {b21, bm1, b22, bm2};
    const int m = blockIdx.x >> 4;
    const int chunk = blockIdx.x & 15;
    unsigned char* dst = g_wbuf[m];
    const float* src = W[m];
    const int r0 = chunk * 8;
    for (int i = threadIdx.x; i < 8 * 68; i += blockDim.x) {
        int r = r0 + i / 68, p = i % 68;
        uint32_t val = 0;
        if (p < 64) {
            float2 v = reinterpret_cast<const float2*>(src)[r * 64 + p];
            val = pack_bf2(v.x, v.y);
        }
        reinterpret_cast<uint32_t*>(dst + r * ROWB)[p] = val;
    }
    if (chunk == 0 && threadIdx.x < 128)
        reinterpret_cast<float*>(dst + 128 * ROWB)[threadIdx.x] = Bv[m][threadIdx.x];
}

// ---------------- cp.async weight staging ----------------------------------
__device__ __forceinline__ void cp_issue(char* sb, int midx, int tid) {
    uint32_t wbase = smem_u32(sb) + OFF_W;
    const unsigned char* g = g_wbuf[midx];
    #pragma unroll
    for (int it = 0; it < 9; ++it) {
        int i = tid + it * THREADS;
        if (i < WBUF_BYTES / 16) {
            asm volatile("cp.async.cg.shared.global [%0], [%1], 16;"
                         :: "r"(wbase + i * 16),
                            "l"(__cvta_generic_to_global(g + i * 16)));
        }
    }
    asm volatile("cp.async.commit_group;");
}

__device__ __forceinline__ void cp_wait() {
    asm volatile("cp.async.wait_group 0;");
    __syncthreads();
}

// ---------------- one 128x128x128 layer, 4x2 warp tiling --------------------
// warp w: rows [32*(w&3), +32), cols [64*(w>>2), +64). out = tanh(in @ W^T + b).
// Bias pre-loaded into the accumulators (MMA accumulates on top).
// Always writes OFF_A; in_off may equal OFF_A (barrier separates read/write).
__device__ __forceinline__ void gemm_tanh(char* sb, int in_off, int warp, int lane) {
    const int rw = warp & 3, cw = warp >> 2;
    const int g = lane >> 2, tg = lane & 3;
    float acc[2][8][4];

    // init accumulators with bias (bias staged alongside W; cp_wait done)
    const float* bias = reinterpret_cast<const float*>(sb + OFF_W + 128 * ROWB);
    #pragma unroll
    for (int t = 0; t < 8; ++t) {
        float2 b = *reinterpret_cast<const float2*>(bias + cw * 64 + t * 8 + tg * 2);
        acc[0][t][0] = b.x; acc[0][t][1] = b.y; acc[0][t][2] = b.x; acc[0][t][3] = b.y;
        acc[1][t][0] = b.x; acc[1][t][1] = b.y; acc[1][t][2] = b.x; acc[1][t][3] = b.y;
    }

    const uint32_t base = smem_u32(sb);
    const int l7 = lane & 7;
    const int rA = (((lane >> 3) & 1) << 3) + l7;
    const int kA = (lane >> 4) << 3;
    uint32_t aaddr0 = base + in_off + (rw * 32 + rA) * ROWB + kA * 2;
    uint32_t aaddr1 = aaddr0 + 16 * ROWB;
    const int rB = (((lane >> 4) & 1) << 3) + l7;
    const int kB = ((lane >> 3) & 1) << 3;
    uint32_t baddr = base + OFF_W + (cw * 64 + rB) * ROWB + kB * 2;

    #pragma unroll
    for (int kk = 0; kk < 8; ++kk) {
        uint32_t a0, a1, a2, a3, a4, a5, a6, a7;
        ldsm4(a0, a1, a2, a3, aaddr0 + kk * 32);
        ldsm4(a4, a5, a6, a7, aaddr1 + kk * 32);
        #pragma unroll
        for (int np = 0; np < 4; ++np) {
            uint32_t b0, b1, b2, b3;
            ldsm4(b0, b1, b2, b3, baddr + np * (16 * ROWB) + kk * 32);
            mma_bf16(acc[0][2*np][0],   acc[0][2*np][1],   acc[0][2*np][2],   acc[0][2*np][3],
                     a0, a1, a2, a3, b0, b1);
            mma_bf16(acc[0][2*np+1][0], acc[0][2*np+1][1], acc[0][2*np+1][2], acc[0][2*np+1][3],
                     a0, a1, a2, a3, b2, b3);
            mma_bf16(acc[1][2*np][0],   acc[1][2*np][1],   acc[1][2*np][2],   acc[1][2*np][3],
                     a4, a5, a6, a7, b0, b1);
            mma_bf16(acc[1][2*np+1][0], acc[1][2*np+1][1], acc[1][2*np+1][2], acc[1][2*np+1][3],
                     a4, a5, a6, a7, b2, b3);
        }
    }
    __syncthreads();  // all warps' reads of in_off/A complete before stores

    #pragma unroll
    for (int mt = 0; mt < 2; ++mt) {
        char* o0 = sb + OFF_A + (rw * 32 + mt * 16 + g) * ROWB + cw * 128;
        #pragma unroll
        for (int t = 0; t < 8; ++t) {
            uint32_t p0 = pack_bf2(tanh_fast(acc[mt][t][0]), tanh_fast(acc[mt][t][1]));
            uint32_t p1 = pack_bf2(tanh_fast(acc[mt][t][2]), tanh_fast(acc[mt][t][3]));
            *reinterpret_cast<uint32_t*>(o0 + (t * 8 + tg * 2) * 2) = p0;
            *reinterpret_cast<uint32_t*>(o0 + 8 * ROWB + (t * 8 + tg * 2) * 2) = p1;
        }
    }
}

__global__ void __launch_bounds__(THREADS, 2)
barriernet_kernel(const float* __restrict__ x,
                  const float* __restrict__ mean_, const float* __restrict__ std_,
                  const float* __restrict__ fc1_w, const float* __restrict__ fc1_b,
                  const float* __restrict__ fc31_w, const float* __restrict__ fc31_b,
                  const float* __restrict__ fc32_w, const float* __restrict__ fc32_b,
                  float* __restrict__ out)
{
    extern __shared__ char sb[];
    const int tid  = threadIdx.x;
    const int warp = tid >> 5;
    const int lane = tid & 31;
    const int row0 = blockIdx.x * ROWS_PER_CTA;

    // ---- stage small constants + x tile ----
    float* xs   = reinterpret_cast<float*>(sb + OFF_X);
    float* w1s  = reinterpret_cast<float*>(sb + OFF_W1);
    float* b1s  = reinterpret_cast<float*>(sb + OFF_B1);
    float* w31s = reinterpret_cast<float*>(sb + OFF_W31);
    float* w32s = reinterpret_cast<float*>(sb + OFF_W32);
    float* sml  = reinterpret_cast<float*>(sb + OFF_SML);
    for (int i = tid; i < 768; i += THREADS) { xs[i] = x[(size_t)row0 * 6 + i]; w1s[i] = fc1_w[i]; }
    for (int i = tid; i < 384; i += THREADS) w31s[i] = fc31_w[i];
    for (int i = tid; i < 256; i += THREADS) w32s[i] = fc32_w[i];
    if (tid < 128) b1s[tid] = fc1_b[tid];
    if (tid < 3)  sml[tid] = fc31_b[tid];
    if (tid >= 3 && tid < 5) sml[tid] = fc32_b[tid - 3];
    if (tid >= 5 && tid < 11) sml[tid] = std_[tid - 5];
    if (tid >= 11 && tid < 17) sml[tid] = mean_[tid - 11];
    __syncthreads();

    // prefetch fc21 weights, overlapped with fc1 compute
    cp_issue(sb, 0, tid);

    // ---- fc1 (K=6) + tanh -> H (bf16) ----
    #pragma unroll
    for (int r = 0; r < 16; ++r) {
        int row = warp * 16 + r;
        const float* xr = &xs[row * 6];
        float x0v = xr[0], x1v = xr[1], x2v = xr[2], x3v = xr[3], x4v = xr[4], x5v = xr[5];
        #pragma unroll
        for (int c = lane; c < 128; c += 32) {
            const float* w = &w1s[c * 6];
            float s = b1s[c] + x0v*w[0] + x1v*w[1] + x2v*w[2] + x3v*w[3] + x4v*w[4] + x5v*w[5];
            *reinterpret_cast<__nv_bfloat16*>(sb + OFF_H + row * ROWB + c * 2) =
                __float2bfloat16_rn(tanh_fast(s));
        }
    }
    cp_wait();  // fc21 staged; barrier also publishes H

    // ---- path 1: fc21 -> fcm1 -> fc31 head ----
    gemm_tanh(sb, OFF_H, warp, lane);
    cp_issue(sb, 1, tid);   // fcm1 (W region free: all MMA reads done pre-store)
    cp_wait();
    gemm_tanh(sb, OFF_A, warp, lane);
    __syncthreads();        // publish A for head reads across warps

    float d0 = 0.f, d1 = 0.f, d2 = 0.f;
    if (lane < 16) {
        int row = warp * 16 + lane;
        const uint32_t* a = reinterpret_cast<const uint32_t*>(sb + OFF_A + row * ROWB);
        d0 = sml[0]; d1 = sml[1]; d2 = sml[2];
        #pragma unroll 8
        for (int i = 0; i < 64; ++i) {
            uint32_t u = a[i];
            float2 av = __bfloat1622float2(*reinterpret_cast<const __nv_bfloat162*>(&u));
            int k = 2 * i;
            d0 += av.x * w31s[k]       + av.y * w31s[k + 1];
            d1 += av.x * w31s[128 + k] + av.y * w31s[128 + k + 1];
            d2 += av.x * w31s[256 + k] + av.y * w31s[256 + k + 1];
        }
    }

    // ---- path 2: fc22 -> fcm2 -> fc32 head + HOCBF/QP epilogue ----
    cp_issue(sb, 2, tid);   // fc22
    cp_wait();
    gemm_tanh(sb, OFF_H, warp, lane);   // internal barrier also fences head1 A-reads
    cp_issue(sb, 3, tid);   // fcm2
    cp_wait();
    gemm_tanh(sb, OFF_A, warp, lane);
    __syncthreads();

    if (lane < 16) {
        int row = warp * 16 + lane;
        const uint32_t* a = reinterpret_cast<const uint32_t*>(sb + OFF_A + row * ROWB);
        float z0 = sml[3], z1 = sml[4];
        #pragma unroll 8
        for (int i = 0; i < 64; ++i) {
            uint32_t u = a[i];
            float2 av = __bfloat1622float2(*reinterpret_cast<const __nv_bfloat162*>(&u));
            int k = 2 * i;
            z0 += av.x * w32s[k]       + av.y * w32s[k + 1];
            z1 += av.x * w32s[128 + k] + av.y * w32s[128 + k + 1];
        }
        float s0 = 4.f / (1.f + expf(-z0));
        float s1 = 4.f / (1.f + expf(-z1));

        const float* xr = &xs[row * 6];
        float px = xr[0] * sml[5] + sml[11];
        float vx = xr[1] * sml[6] + sml[12];
        float py = xr[2] * sml[7] + sml[13];
        float vy = xr[3] * sml[8] + sml[14];
        float pz = xr[4] * sml[9] + sml[15];
        float vz = xr[5] * sml[10] + sml[16];

        float dx = px - 10.f, dy = py - 10.f, dz = pz - 9.f;
        float dx2 = dx*dx, dy2 = dy*dy, dz2 = dz*dz;
        float dx3 = dx2*dx, dy3 = dy2*dy, dz3 = dz2*dz;
        float barrier = dx2*dx2 + dy2*dy2 + dz2*dz2 - 2401.f;  // R^4
        float bdot = 4.f * (dx3*vx + dy3*vy + dz3*vz);
        float Lf2b = 12.f * (dx2*vx*vx + dy2*vy*vy + dz2*vz*vz);
        float Gx = -4.f*dx3, Gy = -4.f*dy3, Gz = -4.f*dz3;
        float hv = Lf2b + (s0 + s1) * bdot + s0 * s1 * barrier;

        float u0 = -d0, u1 = -d1, u2 = -d2;
        float Gu = Gx*u0 + Gy*u1 + Gz*u2;
        float GG = Gx*Gx + Gy*Gy + Gz*Gz;
        float lam = fmaxf(Gu - hv, 0.f) / GG;

        float* o = out + (size_t)(row0 + row) * 3;
        o[0] = u0 - lam * Gx;
        o[1] = u1 - lam * Gy;
        o[2] = u2 - lam * Gz;
    }
}

extern "C" void kernel_launch(void* const* d_in, const int* in_sizes, int n_in,
                              void* d_out, int out_size) {
    const float* x      = (const float*)d_in[0];
    const float* mean_  = (const float*)d_in[1];
    const float* std_   = (const float*)d_in[2];
    const float* fc1_w  = (const float*)d_in[3];
    const float* fc1_b  = (const float*)d_in[4];
    const float* fc21_w = (const float*)d_in[5];
    const float* fc21_b = (const float*)d_in[6];
    const float* fc22_w = (const float*)d_in[7];
    const float* fc22_b = (const float*)d_in[8];
    const float* fcm1_w = (const float*)d_in[9];
    const float* fcm1_b = (const float*)d_in[10];
    const float* fcm2_w = (const float*)d_in[11];
    const float* fcm2_b = (const float*)d_in[12];
    const float* fc31_w = (const float*)d_in[13];
    const float* fc31_b = (const float*)d_in[14];
    const float* fc32_w = (const float*)d_in[15];
    const float* fc32_b = (const float*)d_in[16];
    float* out = (float*)d_out;

    int B = in_sizes[0] / 6;
    int grid = B / ROWS_PER_CTA;

    prep_weights<<<64, 256>>>(fc21_w, fc21_b, fcm1_w, fcm1_b,
                              fc22_w, fc22_b, fcm2_w, fcm2_b);

    cudaFuncSetAttribute(barriernet_kernel,
                         cudaFuncAttributeMaxDynamicSharedMemorySize, SMEM_BYTES);
    barriernet_kernel<<<grid, THREADS, SMEM_BYTES>>>(
        x, mean_, std_, fc1_w, fc1_b, fc31_w, fc31_b, fc32_w, fc32_b, out);
}